// round 12
// baseline (speedup 1.0000x reference)
#include <cuda_runtime.h>
#include <cstdint>

// Problem constants
#define BB   8
#define NN   64
#define DD   128
#define HH   4
#define FFD  512
#define ROWS (BB*NN*NN)   // 32768
#define LAYERS 3

// ---------------- scratch (device globals; no runtime allocation) ----------------
__device__ float g_tok[(size_t)ROWS*DD];     // token state
__device__ float g_big[(size_t)ROWS*FFD];    // qkv (packed) OR ffn hidden
__device__ float g_o  [(size_t)ROWS*DD];     // attention output
__device__ float g_tmp[(size_t)ROWS*DD];     // pre-LN scratch
// weight planes: B_T as bf16x2 pair-words, [L][N][K/2]
__device__ uint32_t g_wqkv_hi[3*512*64], g_wqkv_lo[3*512*64];
__device__ uint32_t g_wo_hi [3*128*64],  g_wo_lo [3*128*64];
__device__ uint32_t g_w1_hi [3*512*64],  g_w1_lo [3*512*64];
__device__ uint32_t g_w2_hi [3*128*256], g_w2_lo [3*128*256];
__device__ int g_maskflag;

// ---------------- bf16 split helper ----------------
__device__ __forceinline__ void split2(float x0, float x1, uint32_t& h, uint32_t& l)
{
    uint32_t hh;
    asm("cvt.rn.bf16x2.f32 %0, %1, %2;" : "=r"(hh) : "f"(x1), "f"(x0));  // lo16=x0, hi16=x1
    float h0 = __uint_as_float(hh << 16);
    float h1 = __uint_as_float(hh & 0xFFFF0000u);
    float l0 = x0 - h0, l1 = x1 - h1;
    uint32_t ll;
    asm("cvt.rn.bf16x2.f32 %0, %1, %2;" : "=r"(ll) : "f"(l1), "f"(l0));
    h = hh; l = ll;
}

__device__ __forceinline__ void mma16(float* c, const uint32_t a[4], uint32_t b0, uint32_t b1)
{
    asm volatile(
        "mma.sync.aligned.m16n8k16.row.col.f32.bf16.bf16.f32 "
        "{%0,%1,%2,%3},{%4,%5,%6,%7},{%8,%9},{%0,%1,%2,%3};"
        : "+f"(c[0]), "+f"(c[1]), "+f"(c[2]), "+f"(c[3])
        : "r"(a[0]), "r"(a[1]), "r"(a[2]), "r"(a[3]), "r"(b0), "r"(b1));
}

// ---------------- edge_mask dtype detection ----------------
__global__ void detect_mask_kernel(const unsigned char* __restrict__ p)
{
    __shared__ int sA, sB;
    if (threadIdx.x == 0) { sA = 0; sB = 0; }
    __syncthreads();
    int a = 0, bn = 0;
    for (int i = threadIdx.x; i < 8192; i += blockDim.x) {
        unsigned char b0 = p[4*i+0], b1 = p[4*i+1], b2 = p[4*i+2], b3 = p[4*i+3];
        a  |= b0;
        bn |= (b1 | b2 | b3);
    }
    if (a)  atomicOr(&sA, 1);
    if (bn) atomicOr(&sB, 1);
    __syncthreads();
    if (threadIdx.x == 0) {
        int f;
        if (sA && sB)  f = 0;   // uint8
        else if (!sB)  f = 1;   // int32
        else           f = 2;   // float32
        g_maskflag = f;
    }
}

// ---------------- token embedding ----------------
__global__ void embed_kernel(const float* __restrict__ x, const float* __restrict__ ea,
                             const void* __restrict__ mask,
                             const float* __restrict__ nW, const float* __restrict__ nb,
                             const float* __restrict__ eW, const float* __restrict__ eb,
                             const float* __restrict__ noe)
{
    int bij = blockIdx.x;
    int j = bij & 63, i = (bij >> 6) & 63, b = bij >> 12;
    int d = threadIdx.x;
    float val;
    if (i == j) {
        val = nb[d];
        const float* xr = x + (size_t)(b*64 + i) * 16;
        #pragma unroll
        for (int c = 0; c < 16; c++) val = fmaf(xr[c], nW[c*128 + d], val);
    } else {
        int f = g_maskflag;
        bool m;
        if (f == 0)      m = ((const unsigned char*)mask)[bij] != 0;
        else if (f == 1) m = ((const int*)mask)[bij] != 0;
        else             m = ((const float*)mask)[bij] != 0.0f;
        if (m) {
            val = eb[d];
            const float* er = ea + (size_t)bij * 8;
            #pragma unroll
            for (int c = 0; c < 8; c++) val = fmaf(er[c], eW[c*128 + d], val);
        } else {
            val = noe[d];
        }
    }
    g_tok[(size_t)bij * 128 + d] = val;
}

// ---------------- weight packing (fp32 [L][K][N] -> planes [L][N][K/2]) ----------------
__global__ void pack_qkv_all(const float* __restrict__ Wq, const float* __restrict__ Wk,
                             const float* __restrict__ Wv1, const float* __restrict__ Wv2,
                             uint32_t* __restrict__ hi, uint32_t* __restrict__ lo)
{
    int idx = blockIdx.x * 256 + threadIdx.x;    // 3*512*64 = 98304
    int l = idx >> 15;
    int rem = idx & 32767;
    int n = rem >> 6, kp = rem & 63;
    int seg = n >> 7, nn = n & 127;
    const float* W = (seg == 0) ? Wq : (seg == 1) ? Wk : (seg == 2) ? Wv1 : Wv2;
    W += (size_t)l * 16384;
    float v0 = W[(2*kp) * 128 + nn], v1 = W[(2*kp+1) * 128 + nn];
    uint32_t h, lw; split2(v0, v1, h, lw);
    hi[idx] = h; lo[idx] = lw;
}

__global__ void pack_w(const float* __restrict__ W, uint32_t* __restrict__ hi,
                       uint32_t* __restrict__ lo, int K, int N)
{
    int idx = blockIdx.x * 256 + threadIdx.x;    // L*N*(K/2)
    int Kw = K >> 1;
    int per = N * Kw;
    int l = idx / per, rem = idx - l * per;
    int n = rem / Kw, kp = rem - n * Kw;
    const float* Wl = W + (size_t)l * K * N;
    float v0 = Wl[(2*kp) * N + n], v1 = Wl[(2*kp+1) * N + n];
    uint32_t h, lw; split2(v0, v1, h, lw);
    hi[idx] = h; lo[idx] = lw;
}

// ---------------- bf16x3 tensor-core GEMM (fp32 A, pre-packed B planes) ----------------
#define PITCH 20
#define ARR   (128*PITCH)      // 2560 words per array
#define STGW  (4*ARR)          // As_hi, As_lo, Bs_hi, Bs_lo
#define GEMM_SMEM (2*STGW*4)   // 81920 bytes

template<bool BIAS, bool RELU, bool RESID>
__global__ void __launch_bounds__(256, 2) gemm_tc(
    const float* __restrict__ A,
    const uint32_t* __restrict__ Bhi, const uint32_t* __restrict__ Blo,
    const float* __restrict__ bias, const float* __restrict__ resid,
    float* __restrict__ C, int K, int N)
{
    extern __shared__ uint32_t smw[];
    uint32_t sbase = (uint32_t)__cvta_generic_to_shared(smw);
    int bm = blockIdx.x, bn = blockIdx.y;
    int t = threadIdx.x, lane = t & 31, w = t >> 5;
    int wm = w & 3, wn = w >> 2, g = lane >> 2, tg = lane & 3;
    int Kw = K >> 1;

    const float*    Ab    = A   + (size_t)bm * 128 * K;
    const uint32_t* Bb_hi = Bhi + (size_t)bn * 128 * Kw;
    const uint32_t* Bb_lo = Blo + (size_t)bn * 128 * Kw;

    int arow = t >> 3, akg4 = t & 7;
    int bnr  = t >> 2, bgrp = t & 3;

    auto cpasyncB = [&](int c, int st) {
        int kp0 = c * 16;
        uint32_t base = sbase + (uint32_t)st * STGW * 4u;
        #pragma unroll
        for (int i = 0; i < 2; i++) {
            int n = bnr + i * 64;
            uint32_t doff = (uint32_t)(n * PITCH + bgrp * 4) * 4u;
            size_t goff = (size_t)n * Kw + kp0 + bgrp * 4;
            asm volatile("cp.async.ca.shared.global [%0],[%1],16;" :: "r"(base + 2*ARR*4 + doff), "l"(Bb_hi + goff));
            asm volatile("cp.async.ca.shared.global [%0],[%1],16;" :: "r"(base + 3*ARR*4 + doff), "l"(Bb_lo + goff));
        }
        asm volatile("cp.async.commit_group;");
    };
    auto ldgA = [&](int c, float4* rq) {
        int k0 = c * 32;
        #pragma unroll
        for (int i = 0; i < 4; i++) {
            int row = arow + i * 32;
            rq[i] = *(const float4*)(Ab + (size_t)row * K + k0 + akg4 * 4);
        }
    };
    auto stsA = [&](const float4* rq, int st) {
        uint32_t* As_hi = smw + st * STGW;
        uint32_t* As_lo = As_hi + ARR;
        #pragma unroll
        for (int i = 0; i < 4; i++) {
            int row = arow + i * 32;
            uint32_t h0, l0, h1, l1;
            split2(rq[i].x, rq[i].y, h0, l0);
            split2(rq[i].z, rq[i].w, h1, l1);
            int off = row * PITCH + akg4 * 2;
            *(uint2*)(As_hi + off) = make_uint2(h0, h1);
            *(uint2*)(As_lo + off) = make_uint2(l0, l1);
        }
    };

    float acc[2][8][4] = {};
    int nch = K >> 5;

    float4 rq[4], rq2[4];
    cpasyncB(0, 0);
    ldgA(0, rq);
    stsA(rq, 0);

    for (int c = 0; c < nch; c++) {
        int st = c & 1;
        bool more = (c + 1 < nch);
        if (more) {
            cpasyncB(c + 1, st ^ 1);
            ldgA(c + 1, rq2);
            asm volatile("cp.async.wait_group 1;");
        } else {
            asm volatile("cp.async.wait_group 0;");
        }
        __syncthreads();

        const uint32_t* sAhi = smw + st * STGW;
        const uint32_t* sAlo = sAhi + ARR;
        const uint32_t* sBhi = sAhi + 2*ARR;
        const uint32_t* sBlo = sAhi + 3*ARR;

        #pragma unroll
        for (int ks = 0; ks < 2; ks++) {
            int kw = ks * 8 + tg;
            uint32_t ah[2][4], al[2][4];
            #pragma unroll
            for (int mt = 0; mt < 2; mt++) {
                int r = wm * 32 + mt * 16 + g;
                ah[mt][0] = sAhi[r*PITCH + kw];       ah[mt][1] = sAhi[(r+8)*PITCH + kw];
                ah[mt][2] = sAhi[r*PITCH + kw + 4];   ah[mt][3] = sAhi[(r+8)*PITCH + kw + 4];
                al[mt][0] = sAlo[r*PITCH + kw];       al[mt][1] = sAlo[(r+8)*PITCH + kw];
                al[mt][2] = sAlo[r*PITCH + kw + 4];   al[mt][3] = sAlo[(r+8)*PITCH + kw + 4];
            }
            #pragma unroll
            for (int nt = 0; nt < 8; nt++) {
                int n = wn * 64 + nt * 8 + g;
                uint32_t bh0 = sBhi[n*PITCH + kw], bh1 = sBhi[n*PITCH + kw + 4];
                uint32_t bl0 = sBlo[n*PITCH + kw], bl1 = sBlo[n*PITCH + kw + 4];
                #pragma unroll
                for (int mt = 0; mt < 2; mt++) {
                    mma16(acc[mt][nt], ah[mt], bh0, bh1);
                    mma16(acc[mt][nt], ah[mt], bl0, bl1);
                    mma16(acc[mt][nt], al[mt], bh0, bh1);
                }
            }
        }
        if (more) stsA(rq2, st ^ 1);
        __syncthreads();
    }

    #pragma unroll
    for (int mt = 0; mt < 2; mt++) {
        int row = bm * 128 + wm * 32 + mt * 16 + g;
        #pragma unroll
        for (int nt = 0; nt < 8; nt++) {
            int col = bn * 128 + wn * 64 + nt * 8 + tg * 2;
            float bx = 0.f, by = 0.f;
            if (BIAS) { float2 b2 = *(const float2*)&bias[col]; bx = b2.x; by = b2.y; }
            #pragma unroll
            for (int rr = 0; rr < 2; rr++) {
                int r = row + rr * 8;
                float v0 = acc[mt][nt][rr * 2 + 0];
                float v1 = acc[mt][nt][rr * 2 + 1];
                if (BIAS) { v0 += bx; v1 += by; }
                if (RELU) { v0 = fmaxf(v0, 0.f); v1 = fmaxf(v1, 0.f); }
                if (RESID) {
                    float2 rv = *(const float2*)&resid[(size_t)r * N + col];
                    v0 += rv.x; v1 += rv.y;
                }
                *(float2*)&C[(size_t)r * N + col] = make_float2(v0, v1);
            }
        }
    }
}

// ---------------- triangular attention (4-i tile, shared q/v1 staging buffer) ----------------
// qkv row layout: [q(0:128) | k(128:256) | v1(256:384) | v2(384:512)]
// smem: qv buffer 4*64*32 fp32 = 32KB (q in pass1, v1 in pass2) + scores 4*64*64 fp32 = 64KB
#define ATTN_SMEM 98304
__global__ void __launch_bounds__(256) attn_kernel(
    const float* __restrict__ qkv, float* __restrict__ o)
{
    extern __shared__ float sm[];
    float* qv_s = sm;            // [4][64][32] — q during pass1, v1 during pass2
    float* s_s  = sm + 8192;     // [4][64][64]

    int bx = blockIdx.x;                 // 8*4*16 = 512 blocks
    int ig = bx & 15, h = (bx >> 4) & 3, b = bx >> 6;
    int i0 = ig * 4;
    int t = threadIdx.x;

    // stage q
    for (int idx = t; idx < 8192; idx += 256) {
        int d = idx & 31, l = (idx >> 5) & 63, ii = idx >> 11;
        qv_s[idx] = qkv[(size_t)((b*64 + i0 + ii) * 64 + l) * 512 + h * 32 + d];
    }
    __syncthreads();

    int j = t >> 2, c = t & 3;
    size_t kvbase = (size_t)(b * 4096 + j) * 512 + h * 32 + c * 8;

    // ---- pass 1: scores ----
    const float* kb = qkv + kvbase + 128;     // k
    for (int l = 0; l < 64; l++) {
        const float4* kp = (const float4*)(kb + (size_t)l * 64 * 512);
        float4 k0 = kp[0], k1 = kp[1];
        float p[4];
        #pragma unroll
        for (int ii = 0; ii < 4; ii++) {
            const float* qp = qv_s + ii * 2048 + l * 32 + c * 8;
            float4 qa = *(const float4*)qp, qb = *(const float4*)(qp + 4);
            p[ii] = qa.x*k0.x + qa.y*k0.y + qa.z*k0.z + qa.w*k0.w
                  + qb.x*k1.x + qb.y*k1.y + qb.z*k1.z + qb.w*k1.w;
            p[ii] += __shfl_xor_sync(0xffffffffu, p[ii], 1);
            p[ii] += __shfl_xor_sync(0xffffffffu, p[ii], 2);
        }
        if (c == 0) {
            #pragma unroll
            for (int ii = 0; ii < 4; ii++) s_s[ii*4096 + l*64 + j] = p[ii];
        }
    }
    __syncthreads();   // pass1 done: q no longer needed, s_s complete

    // restage: v1 over the q buffer
    for (int idx = t; idx < 8192; idx += 256) {
        int d = idx & 31, l = (idx >> 5) & 63, ii = idx >> 11;
        qv_s[idx] = qkv[(size_t)((b*64 + i0 + ii) * 64 + l) * 512 + 256 + h * 32 + d];
    }

    // softmax over l (all 256 threads: 4 ii x 64 jj) — touches only s_s
    {
        int ii = t >> 6, jj = t & 63;
        float* col = s_s + ii * 4096 + jj;
        const float invs = 0.17677669529663687f;   // 1/sqrt(32)
        float m = -1e30f;
        for (int l = 0; l < 64; l++) { float v = col[l*64] * invs; col[l*64] = v; m = fmaxf(m, v); }
        float z = 0.f;
        for (int l = 0; l < 64; l++) { float e = __expf(col[l*64] - m); col[l*64] = e; z += e; }
        float iz = 1.f / z;
        for (int l = 0; l < 64; l++) col[l*64] *= iz;
    }
    __syncthreads();

    // ---- pass 2: output ----
    float oacc[4][8] = {};
    const float* v2b = qkv + kvbase + 384;    // v2
    for (int l = 0; l < 64; l++) {
        const float4* vp = (const float4*)(v2b + (size_t)l * 64 * 512);
        float4 va = vp[0], vb = vp[1];
        float vf[8] = {va.x, va.y, va.z, va.w, vb.x, vb.y, vb.z, vb.w};
        #pragma unroll
        for (int ii = 0; ii < 4; ii++) {
            float a = s_s[ii*4096 + l*64 + j];
            const float* up = qv_s + ii*2048 + l*32 + c*8;
            float4 u0 = *(const float4*)up, u1 = *(const float4*)(up + 4);
            float uu[8] = {u0.x, u0.y, u0.z, u0.w, u1.x, u1.y, u1.z, u1.w};
            #pragma unroll
            for (int dd = 0; dd < 8; dd++)
                oacc[ii][dd] = fmaf(a * uu[dd], vf[dd], oacc[ii][dd]);
        }
    }
    #pragma unroll
    for (int ii = 0; ii < 4; ii++) {
        float* op = o + (size_t)((b*64 + i0 + ii) * 64 + j) * 128 + h * 32 + c * 8;
        *(float4*)(op)     = make_float4(oacc[ii][0], oacc[ii][1], oacc[ii][2], oacc[ii][3]);
        *(float4*)(op + 4) = make_float4(oacc[ii][4], oacc[ii][5], oacc[ii][6], oacc[ii][7]);
    }
}

// ---------------- LayerNorm over D=128 ----------------
__global__ void ln_kernel(const float* __restrict__ in, const float* __restrict__ gg,
                          const float* __restrict__ bb, float* __restrict__ out)
{
    size_t row = blockIdx.x;
    int t = threadIdx.x;
    float v = in[row * 128 + t];
    float s = v, s2 = v * v;
    #pragma unroll
    for (int off = 16; off; off >>= 1) {
        s  += __shfl_xor_sync(0xffffffffu, s,  off);
        s2 += __shfl_xor_sync(0xffffffffu, s2, off);
    }
    __shared__ float ws[4], ws2[4];
    if ((t & 31) == 0) { ws[t >> 5] = s; ws2[t >> 5] = s2; }
    __syncthreads();
    s  = ws[0]  + ws[1]  + ws[2]  + ws[3];
    s2 = ws2[0] + ws2[1] + ws2[2] + ws2[3];
    float mean = s * (1.f / 128.f);
    float var  = s2 * (1.f / 128.f) - mean * mean;
    float rs   = rsqrtf(var + 1e-5f);
    out[row * 128 + t] = (v - mean) * rs * gg[t] + bb[t];
}

// ---------------- final diagonal readout ----------------
__global__ void out_kernel(const float* __restrict__ Wout, const float* __restrict__ bout,
                           float* __restrict__ out)
{
    int row = blockIdx.x;
    int b = row >> 6, n = row & 63;
    int t = threadIdx.x;
    float v = g_tok[((size_t)((b*64 + n) * 64 + n)) * 128 + t] * Wout[t];
    #pragma unroll
    for (int off = 16; off; off >>= 1) v += __shfl_xor_sync(0xffffffffu, v, off);
    __shared__ float ws[4];
    if ((t & 31) == 0) ws[t >> 5] = v;
    __syncthreads();
    if (t == 0) out[row] = ws[0] + ws[1] + ws[2] + ws[3] + bout[0];
}

// ---------------- host launcher ----------------
extern "C" void kernel_launch(void* const* d_in, const int* in_sizes, int n_in,
                              void* d_out, int out_size)
{
    const float* x         = (const float*)d_in[0];
    const float* edge_attr = (const float*)d_in[1];
    const void*  edge_mask = (const void*) d_in[2];
    const float* node_W    = (const float*)d_in[3];
    const float* node_b    = (const float*)d_in[4];
    const float* edge_W    = (const float*)d_in[5];
    const float* edge_b    = (const float*)d_in[6];
    const float* no_edge   = (const float*)d_in[7];
    const float* Wq        = (const float*)d_in[8];
    const float* Wk        = (const float*)d_in[9];
    const float* Wv1       = (const float*)d_in[10];
    const float* Wv2       = (const float*)d_in[11];
    const float* Wo        = (const float*)d_in[12];
    const float* bo        = (const float*)d_in[13];
    const float* ln1_g     = (const float*)d_in[14];
    const float* ln1_b     = (const float*)d_in[15];
    const float* W1        = (const float*)d_in[16];
    const float* b1        = (const float*)d_in[17];
    const float* W2        = (const float*)d_in[18];
    const float* b2        = (const float*)d_in[19];
    const float* ln2_g     = (const float*)d_in[20];
    const float* ln2_b     = (const float*)d_in[21];
    const float* Wout      = (const float*)d_in[22];
    const float* bout      = (const float*)d_in[23];

    float *tokp, *bigp, *op, *tmpp;
    uint32_t *wqkv_hi, *wqkv_lo, *wo_hi, *wo_lo, *w1_hi, *w1_lo, *w2_hi, *w2_lo;
    cudaGetSymbolAddress((void**)&tokp, g_tok);
    cudaGetSymbolAddress((void**)&bigp, g_big);
    cudaGetSymbolAddress((void**)&op,   g_o);
    cudaGetSymbolAddress((void**)&tmpp, g_tmp);
    cudaGetSymbolAddress((void**)&wqkv_hi, g_wqkv_hi); cudaGetSymbolAddress((void**)&wqkv_lo, g_wqkv_lo);
    cudaGetSymbolAddress((void**)&wo_hi,  g_wo_hi);    cudaGetSymbolAddress((void**)&wo_lo,  g_wo_lo);
    cudaGetSymbolAddress((void**)&w1_hi,  g_w1_hi);    cudaGetSymbolAddress((void**)&w1_lo,  g_w1_lo);
    cudaGetSymbolAddress((void**)&w2_hi,  g_w2_hi);    cudaGetSymbolAddress((void**)&w2_lo,  g_w2_lo);

    cudaFuncSetAttribute(attn_kernel, cudaFuncAttributeMaxDynamicSharedMemorySize, ATTN_SMEM);
    cudaFuncSetAttribute(gemm_tc<false,false,false>, cudaFuncAttributeMaxDynamicSharedMemorySize, GEMM_SMEM);
    cudaFuncSetAttribute(gemm_tc<true,false,true>,   cudaFuncAttributeMaxDynamicSharedMemorySize, GEMM_SMEM);
    cudaFuncSetAttribute(gemm_tc<true,true,false>,   cudaFuncAttributeMaxDynamicSharedMemorySize, GEMM_SMEM);

    detect_mask_kernel<<<1, 256>>>((const unsigned char*)edge_mask);
    pack_qkv_all<<<384, 256>>>(Wq, Wk, Wv1, Wv2, wqkv_hi, wqkv_lo);
    pack_w<<<96, 256>>> (Wo, wo_hi, wo_lo, 128, 128);
    pack_w<<<384, 256>>>(W1, w1_hi, w1_lo, 128, 512);
    pack_w<<<384, 256>>>(W2, w2_hi, w2_lo, 512, 128);
    embed_kernel<<<ROWS, 128>>>(x, edge_attr, edge_mask, node_W, node_b, edge_W, edge_b, no_edge);

    const dim3 gN128(ROWS / 128, 1);
    const dim3 gN512(ROWS / 128, 4);

    for (int l = 0; l < LAYERS; l++) {
        // fused QKV projection: tok[R,128] @ Wqkv[128,512] -> big
        gemm_tc<false,false,false><<<gN512, 256, GEMM_SMEM>>>(
            tokp, wqkv_hi + l*32768, wqkv_lo + l*32768, nullptr, nullptr, bigp, 128, 512);

        attn_kernel<<<512, 256, ATTN_SMEM>>>(bigp, op);

        // pre-LN1 = tok + o@Wo + bo -> tmp
        gemm_tc<true,false,true><<<gN128, 256, GEMM_SMEM>>>(
            op, wo_hi + l*8192, wo_lo + l*8192, bo + l*128, tokp, tmpp, 128, 128);
        ln_kernel<<<ROWS, 128>>>(tmpp, ln1_g + l*128, ln1_b + l*128, tokp);

        // FFN up (bias+relu)
        gemm_tc<true,true,false><<<gN512, 256, GEMM_SMEM>>>(
            tokp, w1_hi + l*32768, w1_lo + l*32768, b1 + l*512, nullptr, bigp, 128, 512);

        // FFN down + resid -> tmp
        gemm_tc<true,false,true><<<gN128, 256, GEMM_SMEM>>>(
            bigp, w2_hi + l*32768, w2_lo + l*32768, b2 + l*128, tokp, tmpp, 512, 128);
        ln_kernel<<<ROWS, 128>>>(tmpp, ln2_g + l*128, ln2_b + l*128, tokp);
    }

    out_kernel<<<BB * NN, 128>>>(Wout, bout, (float*)d_out);
}

// round 14
// speedup vs baseline: 1.6319x; 1.6319x over previous
#include <cuda_runtime.h>
#include <cstdint>

// Problem constants
#define BB   8
#define NN   64
#define DD   128
#define HH   4
#define FFD  512
#define ROWS (BB*NN*NN)   // 32768
#define LAYERS 3

// ---------------- scratch (device globals; no runtime allocation) ----------------
__device__ float g_tok[(size_t)ROWS*DD];     // token state
__device__ float g_big[(size_t)ROWS*FFD];    // qkv (packed) OR ffn hidden
__device__ float g_o  [(size_t)ROWS*DD];     // attention output
// weight planes: B_T as bf16x2 pair-words, [L][N][K/2]
__device__ uint32_t g_wqkv_hi[3*512*64], g_wqkv_lo[3*512*64];
__device__ uint32_t g_wo_hi [3*128*64],  g_wo_lo [3*128*64];
__device__ uint32_t g_w1_hi [3*512*64],  g_w1_lo [3*512*64];
__device__ uint32_t g_w2_hi [3*128*256], g_w2_lo [3*128*256];
__device__ int g_maskflag;

// ---------------- bf16 split helper ----------------
__device__ __forceinline__ void split2(float x0, float x1, uint32_t& h, uint32_t& l)
{
    uint32_t hh;
    asm("cvt.rn.bf16x2.f32 %0, %1, %2;" : "=r"(hh) : "f"(x1), "f"(x0));  // lo16=x0, hi16=x1
    float h0 = __uint_as_float(hh << 16);
    float h1 = __uint_as_float(hh & 0xFFFF0000u);
    float l0 = x0 - h0, l1 = x1 - h1;
    uint32_t ll;
    asm("cvt.rn.bf16x2.f32 %0, %1, %2;" : "=r"(ll) : "f"(l1), "f"(l0));
    h = hh; l = ll;
}

__device__ __forceinline__ void mma16(float* c, const uint32_t a[4], uint32_t b0, uint32_t b1)
{
    asm volatile(
        "mma.sync.aligned.m16n8k16.row.col.f32.bf16.bf16.f32 "
        "{%0,%1,%2,%3},{%4,%5,%6,%7},{%8,%9},{%0,%1,%2,%3};"
        : "+f"(c[0]), "+f"(c[1]), "+f"(c[2]), "+f"(c[3])
        : "r"(a[0]), "r"(a[1]), "r"(a[2]), "r"(a[3]), "r"(b0), "r"(b1));
}

// ---------------- edge_mask dtype detection ----------------
__global__ void detect_mask_kernel(const unsigned char* __restrict__ p)
{
    __shared__ int sA, sB;
    if (threadIdx.x == 0) { sA = 0; sB = 0; }
    __syncthreads();
    int a = 0, bn = 0;
    for (int i = threadIdx.x; i < 8192; i += blockDim.x) {
        unsigned char b0 = p[4*i+0], b1 = p[4*i+1], b2 = p[4*i+2], b3 = p[4*i+3];
        a  |= b0;
        bn |= (b1 | b2 | b3);
    }
    if (a)  atomicOr(&sA, 1);
    if (bn) atomicOr(&sB, 1);
    __syncthreads();
    if (threadIdx.x == 0) {
        int f;
        if (sA && sB)  f = 0;   // uint8
        else if (!sB)  f = 1;   // int32
        else           f = 2;   // float32
        g_maskflag = f;
    }
}

// ---------------- token embedding ----------------
__global__ void embed_kernel(const float* __restrict__ x, const float* __restrict__ ea,
                             const void* __restrict__ mask,
                             const float* __restrict__ nW, const float* __restrict__ nb,
                             const float* __restrict__ eW, const float* __restrict__ eb,
                             const float* __restrict__ noe)
{
    int bij = blockIdx.x;
    int j = bij & 63, i = (bij >> 6) & 63, b = bij >> 12;
    int d = threadIdx.x;
    float val;
    if (i == j) {
        val = nb[d];
        const float* xr = x + (size_t)(b*64 + i) * 16;
        #pragma unroll
        for (int c = 0; c < 16; c++) val = fmaf(xr[c], nW[c*128 + d], val);
    } else {
        int f = g_maskflag;
        bool m;
        if (f == 0)      m = ((const unsigned char*)mask)[bij] != 0;
        else if (f == 1) m = ((const int*)mask)[bij] != 0;
        else             m = ((const float*)mask)[bij] != 0.0f;
        if (m) {
            val = eb[d];
            const float* er = ea + (size_t)bij * 8;
            #pragma unroll
            for (int c = 0; c < 8; c++) val = fmaf(er[c], eW[c*128 + d], val);
        } else {
            val = noe[d];
        }
    }
    g_tok[(size_t)bij * 128 + d] = val;
}

// ---------------- weight packing (fp32 [L][K][N] -> planes [L][N][K/2]) ----------------
__global__ void pack_qkv_all(const float* __restrict__ Wq, const float* __restrict__ Wk,
                             const float* __restrict__ Wv1, const float* __restrict__ Wv2,
                             uint32_t* __restrict__ hi, uint32_t* __restrict__ lo)
{
    int idx = blockIdx.x * 256 + threadIdx.x;    // 3*512*64 = 98304
    int l = idx >> 15;
    int rem = idx & 32767;
    int n = rem >> 6, kp = rem & 63;
    int seg = n >> 7, nn = n & 127;
    const float* W = (seg == 0) ? Wq : (seg == 1) ? Wk : (seg == 2) ? Wv1 : Wv2;
    W += (size_t)l * 16384;
    float v0 = W[(2*kp) * 128 + nn], v1 = W[(2*kp+1) * 128 + nn];
    uint32_t h, lw; split2(v0, v1, h, lw);
    hi[idx] = h; lo[idx] = lw;
}

__global__ void pack_w(const float* __restrict__ W, uint32_t* __restrict__ hi,
                       uint32_t* __restrict__ lo, int K, int N)
{
    int idx = blockIdx.x * 256 + threadIdx.x;    // L*N*(K/2)
    int Kw = K >> 1;
    int per = N * Kw;
    int l = idx / per, rem = idx - l * per;
    int n = rem / Kw, kp = rem - n * Kw;
    const float* Wl = W + (size_t)l * K * N;
    float v0 = Wl[(2*kp) * N + n], v1 = Wl[(2*kp+1) * N + n];
    uint32_t h, lw; split2(v0, v1, h, lw);
    hi[idx] = h; lo[idx] = lw;
}

// ---------------- bf16x3 tensor-core GEMM (fp32 A, pre-packed B planes) ----------------
// Optional fused row-LayerNorm epilogue (requires N == 128, gridDim.y == 1).
#define PITCH 20
#define ARR   (128*PITCH)      // 2560 words per array
#define STGW  (4*ARR)          // As_hi, As_lo, Bs_hi, Bs_lo
#define GEMM_SMEM (2*STGW*4)   // 81920 bytes

template<bool BIAS, bool RELU, bool RESID, bool LNORM>
__global__ void __launch_bounds__(256, 2) gemm_tc(
    const float* __restrict__ A,
    const uint32_t* __restrict__ Bhi, const uint32_t* __restrict__ Blo,
    const float* __restrict__ bias, const float* __restrict__ resid,
    const float* __restrict__ lng, const float* __restrict__ lnb,
    float* __restrict__ C, int K, int N)
{
    extern __shared__ uint32_t smw[];
    uint32_t sbase = (uint32_t)__cvta_generic_to_shared(smw);
    int bm = blockIdx.x, bn = blockIdx.y;
    int t = threadIdx.x, lane = t & 31, w = t >> 5;
    int wm = w & 3, wn = w >> 2, g = lane >> 2, tg = lane & 3;
    int Kw = K >> 1;

    const float*    Ab    = A   + (size_t)bm * 128 * K;
    const uint32_t* Bb_hi = Bhi + (size_t)bn * 128 * Kw;
    const uint32_t* Bb_lo = Blo + (size_t)bn * 128 * Kw;

    int arow = t >> 3, akg4 = t & 7;
    int bnr  = t >> 2, bgrp = t & 3;

    auto cpasyncB = [&](int c, int st) {
        int kp0 = c * 16;
        uint32_t base = sbase + (uint32_t)st * STGW * 4u;
        #pragma unroll
        for (int i = 0; i < 2; i++) {
            int n = bnr + i * 64;
            uint32_t doff = (uint32_t)(n * PITCH + bgrp * 4) * 4u;
            size_t goff = (size_t)n * Kw + kp0 + bgrp * 4;
            asm volatile("cp.async.ca.shared.global [%0],[%1],16;" :: "r"(base + 2*ARR*4 + doff), "l"(Bb_hi + goff));
            asm volatile("cp.async.ca.shared.global [%0],[%1],16;" :: "r"(base + 3*ARR*4 + doff), "l"(Bb_lo + goff));
        }
        asm volatile("cp.async.commit_group;");
    };
    auto ldgA = [&](int c, float4* rq) {
        int k0 = c * 32;
        #pragma unroll
        for (int i = 0; i < 4; i++) {
            int row = arow + i * 32;
            rq[i] = *(const float4*)(Ab + (size_t)row * K + k0 + akg4 * 4);
        }
    };
    auto stsA = [&](const float4* rq, int st) {
        uint32_t* As_hi = smw + st * STGW;
        uint32_t* As_lo = As_hi + ARR;
        #pragma unroll
        for (int i = 0; i < 4; i++) {
            int row = arow + i * 32;
            uint32_t h0, l0, h1, l1;
            split2(rq[i].x, rq[i].y, h0, l0);
            split2(rq[i].z, rq[i].w, h1, l1);
            int off = row * PITCH + akg4 * 2;
            *(uint2*)(As_hi + off) = make_uint2(h0, h1);
            *(uint2*)(As_lo + off) = make_uint2(l0, l1);
        }
    };

    float acc[2][8][4] = {};
    int nch = K >> 5;

    float4 rq[4], rq2[4];
    cpasyncB(0, 0);
    ldgA(0, rq);
    stsA(rq, 0);

    for (int c = 0; c < nch; c++) {
        int st = c & 1;
        bool more = (c + 1 < nch);
        if (more) {
            cpasyncB(c + 1, st ^ 1);
            ldgA(c + 1, rq2);
            asm volatile("cp.async.wait_group 1;");
        } else {
            asm volatile("cp.async.wait_group 0;");
        }
        __syncthreads();

        const uint32_t* sAhi = smw + st * STGW;
        const uint32_t* sAlo = sAhi + ARR;
        const uint32_t* sBhi = sAhi + 2*ARR;
        const uint32_t* sBlo = sAhi + 3*ARR;

        #pragma unroll
        for (int ks = 0; ks < 2; ks++) {
            int kw = ks * 8 + tg;
            uint32_t ah[2][4], al[2][4];
            #pragma unroll
            for (int mt = 0; mt < 2; mt++) {
                int r = wm * 32 + mt * 16 + g;
                ah[mt][0] = sAhi[r*PITCH + kw];       ah[mt][1] = sAhi[(r+8)*PITCH + kw];
                ah[mt][2] = sAhi[r*PITCH + kw + 4];   ah[mt][3] = sAhi[(r+8)*PITCH + kw + 4];
                al[mt][0] = sAlo[r*PITCH + kw];       al[mt][1] = sAlo[(r+8)*PITCH + kw];
                al[mt][2] = sAlo[r*PITCH + kw + 4];   al[mt][3] = sAlo[(r+8)*PITCH + kw + 4];
            }
            #pragma unroll
            for (int nt = 0; nt < 8; nt++) {
                int n = wn * 64 + nt * 8 + g;
                uint32_t bh0 = sBhi[n*PITCH + kw], bh1 = sBhi[n*PITCH + kw + 4];
                uint32_t bl0 = sBlo[n*PITCH + kw], bl1 = sBlo[n*PITCH + kw + 4];
                #pragma unroll
                for (int mt = 0; mt < 2; mt++) {
                    mma16(acc[mt][nt], ah[mt], bh0, bh1);
                    mma16(acc[mt][nt], ah[mt], bl0, bl1);
                    mma16(acc[mt][nt], al[mt], bh0, bh1);
                }
            }
        }
        if (more) stsA(rq2, st ^ 1);
        __syncthreads();
    }

    if (!LNORM) {
        #pragma unroll
        for (int mt = 0; mt < 2; mt++) {
            int row = bm * 128 + wm * 32 + mt * 16 + g;
            #pragma unroll
            for (int nt = 0; nt < 8; nt++) {
                int col = bn * 128 + wn * 64 + nt * 8 + tg * 2;
                float bx = 0.f, by = 0.f;
                if (BIAS) { float2 b2 = *(const float2*)&bias[col]; bx = b2.x; by = b2.y; }
                #pragma unroll
                for (int rr = 0; rr < 2; rr++) {
                    int r = row + rr * 8;
                    float v0 = acc[mt][nt][rr * 2 + 0];
                    float v1 = acc[mt][nt][rr * 2 + 1];
                    if (BIAS) { v0 += bx; v1 += by; }
                    if (RELU) { v0 = fmaxf(v0, 0.f); v1 = fmaxf(v1, 0.f); }
                    if (RESID) {
                        float2 rv = *(const float2*)&resid[(size_t)r * N + col];
                        v0 += rv.x; v1 += rv.y;
                    }
                    *(float2*)&C[(size_t)r * N + col] = make_float2(v0, v1);
                }
            }
        }
    } else {
        // ----- fused row LayerNorm epilogue (N == 128, gridDim.y == 1) -----
        // step 1: bias + resid into acc; per-thread partial row sums
        float sp[2][2] = {}, qp[2][2] = {};
        #pragma unroll
        for (int mt = 0; mt < 2; mt++) {
            int row = bm * 128 + wm * 32 + mt * 16 + g;
            #pragma unroll
            for (int nt = 0; nt < 8; nt++) {
                int col = wn * 64 + nt * 8 + tg * 2;
                float bx = 0.f, by = 0.f;
                if (BIAS) { float2 b2 = *(const float2*)&bias[col]; bx = b2.x; by = b2.y; }
                #pragma unroll
                for (int rr = 0; rr < 2; rr++) {
                    int r = row + rr * 8;
                    float v0 = acc[mt][nt][rr * 2 + 0] + bx;
                    float v1 = acc[mt][nt][rr * 2 + 1] + by;
                    if (RESID) {
                        float2 rv = *(const float2*)&resid[(size_t)r * 128 + col];
                        v0 += rv.x; v1 += rv.y;
                    }
                    acc[mt][nt][rr * 2 + 0] = v0;
                    acc[mt][nt][rr * 2 + 1] = v1;
                    sp[mt][rr] += v0 + v1;
                    qp[mt][rr] += v0 * v0 + v1 * v1;
                }
            }
        }
        // step 2: quad reduce over tg; combine the two wn-warps via smem
        float* red  = (float*)smw;          // [128][2] sums
        float* red2 = (float*)smw + 256;    // [128][2] sumsq
        #pragma unroll
        for (int mt = 0; mt < 2; mt++)
            #pragma unroll
            for (int rr = 0; rr < 2; rr++) {
                float s = sp[mt][rr], q = qp[mt][rr];
                s += __shfl_xor_sync(0xffffffffu, s, 1);
                s += __shfl_xor_sync(0xffffffffu, s, 2);
                q += __shfl_xor_sync(0xffffffffu, q, 1);
                q += __shfl_xor_sync(0xffffffffu, q, 2);
                if (tg == 0) {
                    int rl = wm * 32 + mt * 16 + g + rr * 8;
                    red [rl * 2 + wn] = s;
                    red2[rl * 2 + wn] = q;
                }
            }
        __syncthreads();
        // step 3: normalize and store
        #pragma unroll
        for (int mt = 0; mt < 2; mt++) {
            #pragma unroll
            for (int rr = 0; rr < 2; rr++) {
                int rl = wm * 32 + mt * 16 + g + rr * 8;
                float S = red[rl * 2] + red[rl * 2 + 1];
                float Q = red2[rl * 2] + red2[rl * 2 + 1];
                float mean = S * (1.f / 128.f);
                float var  = Q * (1.f / 128.f) - mean * mean;
                float rs   = rsqrtf(var + 1e-5f);
                int r = bm * 128 + rl;
                #pragma unroll
                for (int nt = 0; nt < 8; nt++) {
                    int col = wn * 64 + nt * 8 + tg * 2;
                    float2 gv = *(const float2*)&lng[col];
                    float2 bv = *(const float2*)&lnb[col];
                    float v0 = (acc[mt][nt][rr * 2 + 0] - mean) * rs * gv.x + bv.x;
                    float v1 = (acc[mt][nt][rr * 2 + 1] - mean) * rs * gv.y + bv.y;
                    *(float2*)&C[(size_t)r * 128 + col] = make_float2(v0, v1);
                }
            }
        }
    }
}

// ---------------- triangular attention (R11 version: qkv stride 512, 2-i tile) ----------------
__global__ void __launch_bounds__(256) attn_kernel(
    const float* __restrict__ qkv, float* __restrict__ o)
{
    extern __shared__ float sm[];
    float* q_s  = sm;          // [2][64][32]
    float* v1_s = sm + 4096;   // [2][64][32]
    float* s_s  = sm + 8192;   // [2][64][64]

    int bx = blockIdx.x;                // 8*4*32 = 1024 blocks
    int ip = bx & 31;
    int h  = (bx >> 5) & 3;
    int b  = bx >> 7;
    int i0 = ip * 2;
    int t  = threadIdx.x;

    #pragma unroll
    for (int ii = 0; ii < 2; ii++) {
        size_t base = ((size_t)((b*64 + i0 + ii) * 64)) * 512 + h * 32;
        for (int idx = t; idx < 2048; idx += 256) {
            int l = idx >> 5, d = idx & 31;
            q_s [ii*2048 + idx] = qkv[base + (size_t)l * 512 + d];          // q
            v1_s[ii*2048 + idx] = qkv[base + 256 + (size_t)l * 512 + d];    // v1
        }
    }
    __syncthreads();

    int j = t >> 2, c = t & 3;
    size_t kvbase = (size_t)(b * 4096) * 512 + h * 32 + c * 8;

    // ---- pass 1: scores ----
    const float* kb = qkv + kvbase + 128;     // k
    for (int l = 0; l < 64; l++) {
        const float4* kp = (const float4*)(kb + (size_t)(l * 64 + j) * 512);
        float4 k0 = kp[0], k1 = kp[1];
        const float4* q0p = (const float4*)(q_s + l * 32 + c * 8);
        float4 qa = q0p[0], qb = q0p[1];
        float p0 = qa.x*k0.x + qa.y*k0.y + qa.z*k0.z + qa.w*k0.w
                 + qb.x*k1.x + qb.y*k1.y + qb.z*k1.z + qb.w*k1.w;
        const float4* q1p = (const float4*)(q_s + 2048 + l * 32 + c * 8);
        float4 qc = q1p[0], qd = q1p[1];
        float p1 = qc.x*k0.x + qc.y*k0.y + qc.z*k0.z + qc.w*k0.w
                 + qd.x*k1.x + qd.y*k1.y + qd.z*k1.z + qd.w*k1.w;
        p0 += __shfl_xor_sync(0xffffffffu, p0, 1);
        p0 += __shfl_xor_sync(0xffffffffu, p0, 2);
        p1 += __shfl_xor_sync(0xffffffffu, p1, 1);
        p1 += __shfl_xor_sync(0xffffffffu, p1, 2);
        if (c == 0) {
            s_s[l * 64 + j]        = p0;
            s_s[4096 + l * 64 + j] = p1;
        }
    }
    __syncthreads();

    // ---- softmax over l ----
    if (t < 128) {
        int ii = t >> 6, jj = t & 63;
        float* col = s_s + ii * 4096 + jj;
        const float invs = 0.17677669529663687f;   // 1/sqrt(32)
        float m = -1e30f;
        for (int l = 0; l < 64; l++) { float v = col[l*64] * invs; col[l*64] = v; m = fmaxf(m, v); }
        float z = 0.f;
        for (int l = 0; l < 64; l++) { float e = __expf(col[l*64] - m); col[l*64] = e; z += e; }
        float iz = 1.f / z;
        for (int l = 0; l < 64; l++) col[l*64] *= iz;
    }
    __syncthreads();

    // ---- pass 2: output ----
    float o0[8] = {0,0,0,0,0,0,0,0};
    float o1[8] = {0,0,0,0,0,0,0,0};
    const float* v2b = qkv + kvbase + 384;    // v2
    for (int l = 0; l < 64; l++) {
        const float4* vp = (const float4*)(v2b + (size_t)(l * 64 + j) * 512);
        float4 va = vp[0], vb = vp[1];
        float kv[8] = {va.x, va.y, va.z, va.w, vb.x, vb.y, vb.z, vb.w};
        float a0 = s_s[l * 64 + j];
        float a1 = s_s[4096 + l * 64 + j];
        const float4* w0 = (const float4*)(v1_s + l * 32 + c * 8);
        float4 u0a = w0[0], u0b = w0[1];
        float u0[8] = {u0a.x, u0a.y, u0a.z, u0a.w, u0b.x, u0b.y, u0b.z, u0b.w};
        const float4* w1 = (const float4*)(v1_s + 2048 + l * 32 + c * 8);
        float4 u1a = w1[0], u1b = w1[1];
        float u1[8] = {u1a.x, u1a.y, u1a.z, u1a.w, u1b.x, u1b.y, u1b.z, u1b.w};
        #pragma unroll
        for (int dd = 0; dd < 8; dd++) {
            o0[dd] = fmaf(a0 * u0[dd], kv[dd], o0[dd]);
            o1[dd] = fmaf(a1 * u1[dd], kv[dd], o1[dd]);
        }
    }
    {
        float* op = o + ((size_t)((b*64 + i0) * 64 + j)) * 128 + h * 32 + c * 8;
        *(float4*)(op)     = make_float4(o0[0], o0[1], o0[2], o0[3]);
        *(float4*)(op + 4) = make_float4(o0[4], o0[5], o0[6], o0[7]);
    }
    {
        float* op = o + ((size_t)((b*64 + i0 + 1) * 64 + j)) * 128 + h * 32 + c * 8;
        *(float4*)(op)     = make_float4(o1[0], o1[1], o1[2], o1[3]);
        *(float4*)(op + 4) = make_float4(o1[4], o1[5], o1[6], o1[7]);
    }
}

// ---------------- final diagonal readout ----------------
__global__ void out_kernel(const float* __restrict__ Wout, const float* __restrict__ bout,
                           float* __restrict__ out)
{
    int row = blockIdx.x;
    int b = row >> 6, n = row & 63;
    int t = threadIdx.x;
    float v = g_tok[((size_t)((b*64 + n) * 64 + n)) * 128 + t] * Wout[t];
    #pragma unroll
    for (int off = 16; off; off >>= 1) v += __shfl_xor_sync(0xffffffffu, v, off);
    __shared__ float ws[4];
    if ((t & 31) == 0) ws[t >> 5] = v;
    __syncthreads();
    if (t == 0) out[row] = ws[0] + ws[1] + ws[2] + ws[3] + bout[0];
}

// ---------------- host launcher ----------------
extern "C" void kernel_launch(void* const* d_in, const int* in_sizes, int n_in,
                              void* d_out, int out_size)
{
    const float* x         = (const float*)d_in[0];
    const float* edge_attr = (const float*)d_in[1];
    const void*  edge_mask = (const void*) d_in[2];
    const float* node_W    = (const float*)d_in[3];
    const float* node_b    = (const float*)d_in[4];
    const float* edge_W    = (const float*)d_in[5];
    const float* edge_b    = (const float*)d_in[6];
    const float* no_edge   = (const float*)d_in[7];
    const float* Wq        = (const float*)d_in[8];
    const float* Wk        = (const float*)d_in[9];
    const float* Wv1       = (const float*)d_in[10];
    const float* Wv2       = (const float*)d_in[11];
    const float* Wo        = (const float*)d_in[12];
    const float* bo        = (const float*)d_in[13];
    const float* ln1_g     = (const float*)d_in[14];
    const float* ln1_b     = (const float*)d_in[15];
    const float* W1        = (const float*)d_in[16];
    const float* b1        = (const float*)d_in[17];
    const float* W2        = (const float*)d_in[18];
    const float* b2        = (const float*)d_in[19];
    const float* ln2_g     = (const float*)d_in[20];
    const float* ln2_b     = (const float*)d_in[21];
    const float* Wout      = (const float*)d_in[22];
    const float* bout      = (const float*)d_in[23];

    float *tokp, *bigp, *op;
    uint32_t *wqkv_hi, *wqkv_lo, *wo_hi, *wo_lo, *w1_hi, *w1_lo, *w2_hi, *w2_lo;
    cudaGetSymbolAddress((void**)&tokp, g_tok);
    cudaGetSymbolAddress((void**)&bigp, g_big);
    cudaGetSymbolAddress((void**)&op,   g_o);
    cudaGetSymbolAddress((void**)&wqkv_hi, g_wqkv_hi); cudaGetSymbolAddress((void**)&wqkv_lo, g_wqkv_lo);
    cudaGetSymbolAddress((void**)&wo_hi,  g_wo_hi);    cudaGetSymbolAddress((void**)&wo_lo,  g_wo_lo);
    cudaGetSymbolAddress((void**)&w1_hi,  g_w1_hi);    cudaGetSymbolAddress((void**)&w1_lo,  g_w1_lo);
    cudaGetSymbolAddress((void**)&w2_hi,  g_w2_hi);    cudaGetSymbolAddress((void**)&w2_lo,  g_w2_lo);

    cudaFuncSetAttribute(attn_kernel, cudaFuncAttributeMaxDynamicSharedMemorySize, 65536);
    cudaFuncSetAttribute(gemm_tc<false,false,false,false>, cudaFuncAttributeMaxDynamicSharedMemorySize, GEMM_SMEM);
    cudaFuncSetAttribute(gemm_tc<true,false,true,true>,    cudaFuncAttributeMaxDynamicSharedMemorySize, GEMM_SMEM);
    cudaFuncSetAttribute(gemm_tc<true,true,false,false>,   cudaFuncAttributeMaxDynamicSharedMemorySize, GEMM_SMEM);

    detect_mask_kernel<<<1, 256>>>((const unsigned char*)edge_mask);
    pack_qkv_all<<<384, 256>>>(Wq, Wk, Wv1, Wv2, wqkv_hi, wqkv_lo);
    pack_w<<<96, 256>>> (Wo, wo_hi, wo_lo, 128, 128);
    pack_w<<<384, 256>>>(W1, w1_hi, w1_lo, 128, 512);
    pack_w<<<384, 256>>>(W2, w2_hi, w2_lo, 512, 128);
    embed_kernel<<<ROWS, 128>>>(x, edge_attr, edge_mask, node_W, node_b, edge_W, edge_b, no_edge);

    const dim3 gN128(ROWS / 128, 1);
    const dim3 gN512(ROWS / 128, 4);

    for (int l = 0; l < LAYERS; l++) {
        // fused QKV projection: tok[R,128] @ Wqkv[128,512] -> big
        gemm_tc<false,false,false,false><<<gN512, 256, GEMM_SMEM>>>(
            tokp, wqkv_hi + l*32768, wqkv_lo + l*32768, nullptr, nullptr,
            nullptr, nullptr, bigp, 128, 512);

        attn_kernel<<<BB * HH * (NN / 2), 256, 65536>>>(bigp, op);

        // tok = LN1(tok + o@Wo + bo)  — LN fused into epilogue, writes tok in place
        gemm_tc<true,false,true,true><<<gN128, 256, GEMM_SMEM>>>(
            op, wo_hi + l*8192, wo_lo + l*8192, bo + l*128, tokp,
            ln1_g + l*128, ln1_b + l*128, tokp, 128, 128);

        // FFN up (bias+relu)
        gemm_tc<true,true,false,false><<<gN512, 256, GEMM_SMEM>>>(
            tokp, w1_hi + l*32768, w1_lo + l*32768, b1 + l*512, nullptr,
            nullptr, nullptr, bigp, 128, 512);

        // tok = LN2(tok + ffn@W2 + b2) — LN fused into epilogue, writes tok in place
        gemm_tc<true,false,true,true><<<gN128, 256, GEMM_SMEM>>>(
            bigp, w2_hi + l*32768, w2_lo + l*32768, b2 + l*128, tokp,
            ln2_g + l*128, ln2_b + l*128, tokp, 512, 128);
    }

    out_kernel<<<BB * NN, 128>>>(Wout, bout, (float*)d_out);
}

// round 15
// speedup vs baseline: 1.7540x; 1.0748x over previous
#include <cuda_runtime.h>
#include <cuda_fp16.h>
#include <cstdint>

// Problem constants
#define BB   8
#define NN   64
#define DD   128
#define HH   4
#define FFD  512
#define ROWS (BB*NN*NN)   // 32768
#define LAYERS 3

// ---------------- scratch (device globals; no runtime allocation) ----------------
__device__ float  g_tok[(size_t)ROWS*DD];     // token state
__device__ float  g_big[(size_t)ROWS*FFD];    // qkv (q,v1 fp32) OR ffn hidden
__device__ __half g_kv2h[(size_t)ROWS*256];   // fp16 mirror: [k(0:128) | v2(128:256)]
__device__ float  g_o  [(size_t)ROWS*DD];     // attention output
// weight planes: B_T as bf16x2 pair-words, [L][N][K/2]
__device__ uint32_t g_wqkv_hi[3*512*64], g_wqkv_lo[3*512*64];
__device__ uint32_t g_wo_hi [3*128*64],  g_wo_lo [3*128*64];
__device__ uint32_t g_w1_hi [3*512*64],  g_w1_lo [3*512*64];
__device__ uint32_t g_w2_hi [3*128*256], g_w2_lo [3*128*256];
__device__ int g_maskflag;

// ---------------- bf16 split helper ----------------
__device__ __forceinline__ void split2(float x0, float x1, uint32_t& h, uint32_t& l)
{
    uint32_t hh;
    asm("cvt.rn.bf16x2.f32 %0, %1, %2;" : "=r"(hh) : "f"(x1), "f"(x0));  // lo16=x0, hi16=x1
    float h0 = __uint_as_float(hh << 16);
    float h1 = __uint_as_float(hh & 0xFFFF0000u);
    float l0 = x0 - h0, l1 = x1 - h1;
    uint32_t ll;
    asm("cvt.rn.bf16x2.f32 %0, %1, %2;" : "=r"(ll) : "f"(l1), "f"(l0));
    h = hh; l = ll;
}

__device__ __forceinline__ void mma16(float* c, const uint32_t a[4], uint32_t b0, uint32_t b1)
{
    asm volatile(
        "mma.sync.aligned.m16n8k16.row.col.f32.bf16.bf16.f32 "
        "{%0,%1,%2,%3},{%4,%5,%6,%7},{%8,%9},{%0,%1,%2,%3};"
        : "+f"(c[0]), "+f"(c[1]), "+f"(c[2]), "+f"(c[3])
        : "r"(a[0]), "r"(a[1]), "r"(a[2]), "r"(a[3]), "r"(b0), "r"(b1));
}

// unpack 8 halves (uint4) -> 8 floats
__device__ __forceinline__ void h8_to_f(const uint4& r, float* f)
{
    float2 a = __half22float2(*(const __half2*)&r.x);
    float2 b = __half22float2(*(const __half2*)&r.y);
    float2 c = __half22float2(*(const __half2*)&r.z);
    float2 d = __half22float2(*(const __half2*)&r.w);
    f[0]=a.x; f[1]=a.y; f[2]=b.x; f[3]=b.y; f[4]=c.x; f[5]=c.y; f[6]=d.x; f[7]=d.y;
}

// ---------------- edge_mask dtype detection ----------------
__global__ void detect_mask_kernel(const unsigned char* __restrict__ p)
{
    __shared__ int sA, sB;
    if (threadIdx.x == 0) { sA = 0; sB = 0; }
    __syncthreads();
    int a = 0, bn = 0;
    for (int i = threadIdx.x; i < 8192; i += blockDim.x) {
        unsigned char b0 = p[4*i+0], b1 = p[4*i+1], b2 = p[4*i+2], b3 = p[4*i+3];
        a  |= b0;
        bn |= (b1 | b2 | b3);
    }
    if (a)  atomicOr(&sA, 1);
    if (bn) atomicOr(&sB, 1);
    __syncthreads();
    if (threadIdx.x == 0) {
        int f;
        if (sA && sB)  f = 0;   // uint8
        else if (!sB)  f = 1;   // int32
        else           f = 2;   // float32
        g_maskflag = f;
    }
}

// ---------------- token embedding ----------------
__global__ void embed_kernel(const float* __restrict__ x, const float* __restrict__ ea,
                             const void* __restrict__ mask,
                             const float* __restrict__ nW, const float* __restrict__ nb,
                             const float* __restrict__ eW, const float* __restrict__ eb,
                             const float* __restrict__ noe)
{
    int bij = blockIdx.x;
    int j = bij & 63, i = (bij >> 6) & 63, b = bij >> 12;
    int d = threadIdx.x;
    float val;
    if (i == j) {
        val = nb[d];
        const float* xr = x + (size_t)(b*64 + i) * 16;
        #pragma unroll
        for (int c = 0; c < 16; c++) val = fmaf(xr[c], nW[c*128 + d], val);
    } else {
        int f = g_maskflag;
        bool m;
        if (f == 0)      m = ((const unsigned char*)mask)[bij] != 0;
        else if (f == 1) m = ((const int*)mask)[bij] != 0;
        else             m = ((const float*)mask)[bij] != 0.0f;
        if (m) {
            val = eb[d];
            const float* er = ea + (size_t)bij * 8;
            #pragma unroll
            for (int c = 0; c < 8; c++) val = fmaf(er[c], eW[c*128 + d], val);
        } else {
            val = noe[d];
        }
    }
    g_tok[(size_t)bij * 128 + d] = val;
}

// ---------------- weight packing (fp32 [L][K][N] -> planes [L][N][K/2]) ----------------
__global__ void pack_qkv_all(const float* __restrict__ Wq, const float* __restrict__ Wk,
                             const float* __restrict__ Wv1, const float* __restrict__ Wv2,
                             uint32_t* __restrict__ hi, uint32_t* __restrict__ lo)
{
    int idx = blockIdx.x * 256 + threadIdx.x;    // 3*512*64 = 98304
    int l = idx >> 15;
    int rem = idx & 32767;
    int n = rem >> 6, kp = rem & 63;
    int seg = n >> 7, nn = n & 127;
    const float* W = (seg == 0) ? Wq : (seg == 1) ? Wk : (seg == 2) ? Wv1 : Wv2;
    W += (size_t)l * 16384;
    float v0 = W[(2*kp) * 128 + nn], v1 = W[(2*kp+1) * 128 + nn];
    uint32_t h, lw; split2(v0, v1, h, lw);
    hi[idx] = h; lo[idx] = lw;
}

__global__ void pack_w(const float* __restrict__ W, uint32_t* __restrict__ hi,
                       uint32_t* __restrict__ lo, int K, int N)
{
    int idx = blockIdx.x * 256 + threadIdx.x;    // L*N*(K/2)
    int Kw = K >> 1;
    int per = N * Kw;
    int l = idx / per, rem = idx - l * per;
    int n = rem / Kw, kp = rem - n * Kw;
    const float* Wl = W + (size_t)l * K * N;
    float v0 = Wl[(2*kp) * N + n], v1 = Wl[(2*kp+1) * N + n];
    uint32_t h, lw; split2(v0, v1, h, lw);
    hi[idx] = h; lo[idx] = lw;
}

// ---------------- bf16x3 tensor-core GEMM (fp32 A, pre-packed B planes) ----------------
// Optional fused row-LayerNorm epilogue (N == 128, gridDim.y == 1).
// Optional HKV epilogue (QKV GEMM, N == 512): col-blocks bn 1 (k) and 3 (v2) are
// written as fp16 into Ch[row][256] instead of fp32 into C.
#define PITCH 20
#define ARR   (128*PITCH)      // 2560 words per array
#define STGW  (4*ARR)          // As_hi, As_lo, Bs_hi, Bs_lo
#define GEMM_SMEM (2*STGW*4)   // 81920 bytes

template<bool BIAS, bool RELU, bool RESID, bool LNORM, bool HKV>
__global__ void __launch_bounds__(256, 2) gemm_tc(
    const float* __restrict__ A,
    const uint32_t* __restrict__ Bhi, const uint32_t* __restrict__ Blo,
    const float* __restrict__ bias, const float* __restrict__ resid,
    const float* __restrict__ lng, const float* __restrict__ lnb,
    float* __restrict__ C, __half* __restrict__ Ch, int K, int N)
{
    extern __shared__ uint32_t smw[];
    uint32_t sbase = (uint32_t)__cvta_generic_to_shared(smw);
    int bm = blockIdx.x, bn = blockIdx.y;
    int t = threadIdx.x, lane = t & 31, w = t >> 5;
    int wm = w & 3, wn = w >> 2, g = lane >> 2, tg = lane & 3;
    int Kw = K >> 1;

    const float*    Ab    = A   + (size_t)bm * 128 * K;
    const uint32_t* Bb_hi = Bhi + (size_t)bn * 128 * Kw;
    const uint32_t* Bb_lo = Blo + (size_t)bn * 128 * Kw;

    int arow = t >> 3, akg4 = t & 7;
    int bnr  = t >> 2, bgrp = t & 3;

    auto cpasyncB = [&](int c, int st) {
        int kp0 = c * 16;
        uint32_t base = sbase + (uint32_t)st * STGW * 4u;
        #pragma unroll
        for (int i = 0; i < 2; i++) {
            int n = bnr + i * 64;
            uint32_t doff = (uint32_t)(n * PITCH + bgrp * 4) * 4u;
            size_t goff = (size_t)n * Kw + kp0 + bgrp * 4;
            asm volatile("cp.async.ca.shared.global [%0],[%1],16;" :: "r"(base + 2*ARR*4 + doff), "l"(Bb_hi + goff));
            asm volatile("cp.async.ca.shared.global [%0],[%1],16;" :: "r"(base + 3*ARR*4 + doff), "l"(Bb_lo + goff));
        }
        asm volatile("cp.async.commit_group;");
    };
    auto ldgA = [&](int c, float4* rq) {
        int k0 = c * 32;
        #pragma unroll
        for (int i = 0; i < 4; i++) {
            int row = arow + i * 32;
            rq[i] = *(const float4*)(Ab + (size_t)row * K + k0 + akg4 * 4);
        }
    };
    auto stsA = [&](const float4* rq, int st) {
        uint32_t* As_hi = smw + st * STGW;
        uint32_t* As_lo = As_hi + ARR;
        #pragma unroll
        for (int i = 0; i < 4; i++) {
            int row = arow + i * 32;
            uint32_t h0, l0, h1, l1;
            split2(rq[i].x, rq[i].y, h0, l0);
            split2(rq[i].z, rq[i].w, h1, l1);
            int off = row * PITCH + akg4 * 2;
            *(uint2*)(As_hi + off) = make_uint2(h0, h1);
            *(uint2*)(As_lo + off) = make_uint2(l0, l1);
        }
    };

    float acc[2][8][4] = {};
    int nch = K >> 5;

    float4 rq[4], rq2[4];
    cpasyncB(0, 0);
    ldgA(0, rq);
    stsA(rq, 0);

    for (int c = 0; c < nch; c++) {
        int st = c & 1;
        bool more = (c + 1 < nch);
        if (more) {
            cpasyncB(c + 1, st ^ 1);
            ldgA(c + 1, rq2);
            asm volatile("cp.async.wait_group 1;");
        } else {
            asm volatile("cp.async.wait_group 0;");
        }
        __syncthreads();

        const uint32_t* sAhi = smw + st * STGW;
        const uint32_t* sAlo = sAhi + ARR;
        const uint32_t* sBhi = sAhi + 2*ARR;
        const uint32_t* sBlo = sAhi + 3*ARR;

        #pragma unroll
        for (int ks = 0; ks < 2; ks++) {
            int kw = ks * 8 + tg;
            uint32_t ah[2][4], al[2][4];
            #pragma unroll
            for (int mt = 0; mt < 2; mt++) {
                int r = wm * 32 + mt * 16 + g;
                ah[mt][0] = sAhi[r*PITCH + kw];       ah[mt][1] = sAhi[(r+8)*PITCH + kw];
                ah[mt][2] = sAhi[r*PITCH + kw + 4];   ah[mt][3] = sAhi[(r+8)*PITCH + kw + 4];
                al[mt][0] = sAlo[r*PITCH + kw];       al[mt][1] = sAlo[(r+8)*PITCH + kw];
                al[mt][2] = sAlo[r*PITCH + kw + 4];   al[mt][3] = sAlo[(r+8)*PITCH + kw + 4];
            }
            #pragma unroll
            for (int nt = 0; nt < 8; nt++) {
                int n = wn * 64 + nt * 8 + g;
                uint32_t bh0 = sBhi[n*PITCH + kw], bh1 = sBhi[n*PITCH + kw + 4];
                uint32_t bl0 = sBlo[n*PITCH + kw], bl1 = sBlo[n*PITCH + kw + 4];
                #pragma unroll
                for (int mt = 0; mt < 2; mt++) {
                    mma16(acc[mt][nt], ah[mt], bh0, bh1);
                    mma16(acc[mt][nt], ah[mt], bl0, bl1);
                    mma16(acc[mt][nt], al[mt], bh0, bh1);
                }
            }
        }
        if (more) stsA(rq2, st ^ 1);
        __syncthreads();
    }

    if (!LNORM) {
        bool half_blk = HKV && (bn & 1);          // bn 1 -> k, bn 3 -> v2
        int  hbase    = (bn == 3) ? 128 : 0;
        #pragma unroll
        for (int mt = 0; mt < 2; mt++) {
            int row = bm * 128 + wm * 32 + mt * 16 + g;
            #pragma unroll
            for (int nt = 0; nt < 8; nt++) {
                int colL = wn * 64 + nt * 8 + tg * 2;
                int col  = bn * 128 + colL;
                float bx = 0.f, by = 0.f;
                if (BIAS) { float2 b2 = *(const float2*)&bias[col]; bx = b2.x; by = b2.y; }
                #pragma unroll
                for (int rr = 0; rr < 2; rr++) {
                    int r = row + rr * 8;
                    float v0 = acc[mt][nt][rr * 2 + 0];
                    float v1 = acc[mt][nt][rr * 2 + 1];
                    if (BIAS) { v0 += bx; v1 += by; }
                    if (RELU) { v0 = fmaxf(v0, 0.f); v1 = fmaxf(v1, 0.f); }
                    if (RESID) {
                        float2 rv = *(const float2*)&resid[(size_t)r * N + col];
                        v0 += rv.x; v1 += rv.y;
                    }
                    if (half_blk) {
                        *(__half2*)&Ch[(size_t)r * 256 + hbase + colL] = __floats2half2_rn(v0, v1);
                    } else {
                        *(float2*)&C[(size_t)r * N + col] = make_float2(v0, v1);
                    }
                }
            }
        }
    } else {
        // ----- fused row LayerNorm epilogue (N == 128, gridDim.y == 1) -----
        float sp[2][2] = {}, qp[2][2] = {};
        #pragma unroll
        for (int mt = 0; mt < 2; mt++) {
            int row = bm * 128 + wm * 32 + mt * 16 + g;
            #pragma unroll
            for (int nt = 0; nt < 8; nt++) {
                int col = wn * 64 + nt * 8 + tg * 2;
                float bx = 0.f, by = 0.f;
                if (BIAS) { float2 b2 = *(const float2*)&bias[col]; bx = b2.x; by = b2.y; }
                #pragma unroll
                for (int rr = 0; rr < 2; rr++) {
                    int r = row + rr * 8;
                    float v0 = acc[mt][nt][rr * 2 + 0] + bx;
                    float v1 = acc[mt][nt][rr * 2 + 1] + by;
                    if (RESID) {
                        float2 rv = *(const float2*)&resid[(size_t)r * 128 + col];
                        v0 += rv.x; v1 += rv.y;
                    }
                    acc[mt][nt][rr * 2 + 0] = v0;
                    acc[mt][nt][rr * 2 + 1] = v1;
                    sp[mt][rr] += v0 + v1;
                    qp[mt][rr] += v0 * v0 + v1 * v1;
                }
            }
        }
        float* red  = (float*)smw;          // [128][2] sums
        float* red2 = (float*)smw + 256;    // [128][2] sumsq
        #pragma unroll
        for (int mt = 0; mt < 2; mt++)
            #pragma unroll
            for (int rr = 0; rr < 2; rr++) {
                float s = sp[mt][rr], q = qp[mt][rr];
                s += __shfl_xor_sync(0xffffffffu, s, 1);
                s += __shfl_xor_sync(0xffffffffu, s, 2);
                q += __shfl_xor_sync(0xffffffffu, q, 1);
                q += __shfl_xor_sync(0xffffffffu, q, 2);
                if (tg == 0) {
                    int rl = wm * 32 + mt * 16 + g + rr * 8;
                    red [rl * 2 + wn] = s;
                    red2[rl * 2 + wn] = q;
                }
            }
        __syncthreads();
        #pragma unroll
        for (int mt = 0; mt < 2; mt++) {
            #pragma unroll
            for (int rr = 0; rr < 2; rr++) {
                int rl = wm * 32 + mt * 16 + g + rr * 8;
                float S = red[rl * 2] + red[rl * 2 + 1];
                float Q = red2[rl * 2] + red2[rl * 2 + 1];
                float mean = S * (1.f / 128.f);
                float var  = Q * (1.f / 128.f) - mean * mean;
                float rs   = rsqrtf(var + 1e-5f);
                int r = bm * 128 + rl;
                #pragma unroll
                for (int nt = 0; nt < 8; nt++) {
                    int col = wn * 64 + nt * 8 + tg * 2;
                    float2 gv = *(const float2*)&lng[col];
                    float2 bv = *(const float2*)&lnb[col];
                    float v0 = (acc[mt][nt][rr * 2 + 0] - mean) * rs * gv.x + bv.x;
                    float v1 = (acc[mt][nt][rr * 2 + 1] - mean) * rs * gv.y + bv.y;
                    *(float2*)&C[(size_t)r * 128 + col] = make_float2(v0, v1);
                }
            }
        }
    }
}

// ---------------- triangular attention (qkv: q/v1 fp32 stride 512, k/v2 fp16 stride 256) ----------------
__global__ void __launch_bounds__(256) attn_kernel(
    const float* __restrict__ qkv, const __half* __restrict__ kv2h, float* __restrict__ o)
{
    extern __shared__ float sm[];
    float* q_s  = sm;          // [2][64][32]
    float* v1_s = sm + 4096;   // [2][64][32]
    float* s_s  = sm + 8192;   // [2][64][64]

    int bx = blockIdx.x;                // 8*4*32 = 1024 blocks
    int ip = bx & 31;
    int h  = (bx >> 5) & 3;
    int b  = bx >> 7;
    int i0 = ip * 2;
    int t  = threadIdx.x;

    #pragma unroll
    for (int ii = 0; ii < 2; ii++) {
        size_t base = ((size_t)((b*64 + i0 + ii) * 64)) * 512 + h * 32;
        for (int idx = t; idx < 2048; idx += 256) {
            int l = idx >> 5, d = idx & 31;
            q_s [ii*2048 + idx] = qkv[base + (size_t)l * 512 + d];          // q
            v1_s[ii*2048 + idx] = qkv[base + 256 + (size_t)l * 512 + d];    // v1
        }
    }
    __syncthreads();

    int j = t >> 2, c = t & 3;
    size_t hbase = (size_t)(b * 4096 + j) * 256 + h * 32 + c * 8;   // half-row layout

    // ---- pass 1: scores (k fp16) ----
    const __half* kb = kv2h + hbase;          // k at offset 0
    for (int l = 0; l < 64; l++) {
        uint4 kr = *(const uint4*)(kb + (size_t)l * 64 * 256);
        float kf[8]; h8_to_f(kr, kf);
        const float* q0p = q_s + l * 32 + c * 8;
        float4 qa = *(const float4*)q0p, qb = *(const float4*)(q0p + 4);
        float p0 = qa.x*kf[0] + qa.y*kf[1] + qa.z*kf[2] + qa.w*kf[3]
                 + qb.x*kf[4] + qb.y*kf[5] + qb.z*kf[6] + qb.w*kf[7];
        const float* q1p = q_s + 2048 + l * 32 + c * 8;
        float4 qc = *(const float4*)q1p, qd = *(const float4*)(q1p + 4);
        float p1 = qc.x*kf[0] + qc.y*kf[1] + qc.z*kf[2] + qc.w*kf[3]
                 + qd.x*kf[4] + qd.y*kf[5] + qd.z*kf[6] + qd.w*kf[7];
        p0 += __shfl_xor_sync(0xffffffffu, p0, 1);
        p0 += __shfl_xor_sync(0xffffffffu, p0, 2);
        p1 += __shfl_xor_sync(0xffffffffu, p1, 1);
        p1 += __shfl_xor_sync(0xffffffffu, p1, 2);
        if (c == 0) {
            s_s[l * 64 + j]        = p0;
            s_s[4096 + l * 64 + j] = p1;
        }
    }
    __syncthreads();

    // ---- softmax over l ----
    if (t < 128) {
        int ii = t >> 6, jj = t & 63;
        float* col = s_s + ii * 4096 + jj;
        const float invs = 0.17677669529663687f;   // 1/sqrt(32)
        float m = -1e30f;
        for (int l = 0; l < 64; l++) { float v = col[l*64] * invs; col[l*64] = v; m = fmaxf(m, v); }
        float z = 0.f;
        for (int l = 0; l < 64; l++) { float e = __expf(col[l*64] - m); col[l*64] = e; z += e; }
        float iz = 1.f / z;
        for (int l = 0; l < 64; l++) col[l*64] *= iz;
    }
    __syncthreads();

    // ---- pass 2: output (v2 fp16) ----
    float o0[8] = {0,0,0,0,0,0,0,0};
    float o1[8] = {0,0,0,0,0,0,0,0};
    const __half* v2b = kv2h + hbase + 128;   // v2 at offset 128
    for (int l = 0; l < 64; l++) {
        uint4 vr = *(const uint4*)(v2b + (size_t)l * 64 * 256);
        float vf[8]; h8_to_f(vr, vf);
        float a0 = s_s[l * 64 + j];
        float a1 = s_s[4096 + l * 64 + j];
        const float* w0 = v1_s + l * 32 + c * 8;
        float4 u0a = *(const float4*)w0, u0b = *(const float4*)(w0 + 4);
        float u0[8] = {u0a.x, u0a.y, u0a.z, u0a.w, u0b.x, u0b.y, u0b.z, u0b.w};
        const float* w1 = v1_s + 2048 + l * 32 + c * 8;
        float4 u1a = *(const float4*)w1, u1b = *(const float4*)(w1 + 4);
        float u1[8] = {u1a.x, u1a.y, u1a.z, u1a.w, u1b.x, u1b.y, u1b.z, u1b.w};
        #pragma unroll
        for (int dd = 0; dd < 8; dd++) {
            o0[dd] = fmaf(a0 * u0[dd], vf[dd], o0[dd]);
            o1[dd] = fmaf(a1 * u1[dd], vf[dd], o1[dd]);
        }
    }
    {
        float* op = o + ((size_t)((b*64 + i0) * 64 + j)) * 128 + h * 32 + c * 8;
        *(float4*)(op)     = make_float4(o0[0], o0[1], o0[2], o0[3]);
        *(float4*)(op + 4) = make_float4(o0[4], o0[5], o0[6], o0[7]);
    }
    {
        float* op = o + ((size_t)((b*64 + i0 + 1) * 64 + j)) * 128 + h * 32 + c * 8;
        *(float4*)(op)     = make_float4(o1[0], o1[1], o1[2], o1[3]);
        *(float4*)(op + 4) = make_float4(o1[4], o1[5], o1[6], o1[7]);
    }
}

// ---------------- final diagonal readout ----------------
__global__ void out_kernel(const float* __restrict__ Wout, const float* __restrict__ bout,
                           float* __restrict__ out)
{
    int row = blockIdx.x;
    int b = row >> 6, n = row & 63;
    int t = threadIdx.x;
    float v = g_tok[((size_t)((b*64 + n) * 64 + n)) * 128 + t] * Wout[t];
    #pragma unroll
    for (int off = 16; off; off >>= 1) v += __shfl_xor_sync(0xffffffffu, v, off);
    __shared__ float ws[4];
    if ((t & 31) == 0) ws[t >> 5] = v;
    __syncthreads();
    if (t == 0) out[row] = ws[0] + ws[1] + ws[2] + ws[3] + bout[0];
}

// ---------------- host launcher ----------------
extern "C" void kernel_launch(void* const* d_in, const int* in_sizes, int n_in,
                              void* d_out, int out_size)
{
    const float* x         = (const float*)d_in[0];
    const float* edge_attr = (const float*)d_in[1];
    const void*  edge_mask = (const void*) d_in[2];
    const float* node_W    = (const float*)d_in[3];
    const float* node_b    = (const float*)d_in[4];
    const float* edge_W    = (const float*)d_in[5];
    const float* edge_b    = (const float*)d_in[6];
    const float* no_edge   = (const float*)d_in[7];
    const float* Wq        = (const float*)d_in[8];
    const float* Wk        = (const float*)d_in[9];
    const float* Wv1       = (const float*)d_in[10];
    const float* Wv2       = (const float*)d_in[11];
    const float* Wo        = (const float*)d_in[12];
    const float* bo        = (const float*)d_in[13];
    const float* ln1_g     = (const float*)d_in[14];
    const float* ln1_b     = (const float*)d_in[15];
    const float* W1        = (const float*)d_in[16];
    const float* b1        = (const float*)d_in[17];
    const float* W2        = (const float*)d_in[18];
    const float* b2        = (const float*)d_in[19];
    const float* ln2_g     = (const float*)d_in[20];
    const float* ln2_b     = (const float*)d_in[21];
    const float* Wout      = (const float*)d_in[22];
    const float* bout      = (const float*)d_in[23];

    float *tokp, *bigp, *op;
    __half* kv2hp;
    uint32_t *wqkv_hi, *wqkv_lo, *wo_hi, *wo_lo, *w1_hi, *w1_lo, *w2_hi, *w2_lo;
    cudaGetSymbolAddress((void**)&tokp, g_tok);
    cudaGetSymbolAddress((void**)&bigp, g_big);
    cudaGetSymbolAddress((void**)&op,   g_o);
    cudaGetSymbolAddress((void**)&kv2hp, g_kv2h);
    cudaGetSymbolAddress((void**)&wqkv_hi, g_wqkv_hi); cudaGetSymbolAddress((void**)&wqkv_lo, g_wqkv_lo);
    cudaGetSymbolAddress((void**)&wo_hi,  g_wo_hi);    cudaGetSymbolAddress((void**)&wo_lo,  g_wo_lo);
    cudaGetSymbolAddress((void**)&w1_hi,  g_w1_hi);    cudaGetSymbolAddress((void**)&w1_lo,  g_w1_lo);
    cudaGetSymbolAddress((void**)&w2_hi,  g_w2_hi);    cudaGetSymbolAddress((void**)&w2_lo,  g_w2_lo);

    cudaFuncSetAttribute(attn_kernel, cudaFuncAttributeMaxDynamicSharedMemorySize, 65536);
    cudaFuncSetAttribute(gemm_tc<false,false,false,false,true>, cudaFuncAttributeMaxDynamicSharedMemorySize, GEMM_SMEM);
    cudaFuncSetAttribute(gemm_tc<true,false,true,true,false>,   cudaFuncAttributeMaxDynamicSharedMemorySize, GEMM_SMEM);
    cudaFuncSetAttribute(gemm_tc<true,true,false,false,false>,  cudaFuncAttributeMaxDynamicSharedMemorySize, GEMM_SMEM);

    detect_mask_kernel<<<1, 256>>>((const unsigned char*)edge_mask);
    pack_qkv_all<<<384, 256>>>(Wq, Wk, Wv1, Wv2, wqkv_hi, wqkv_lo);
    pack_w<<<96, 256>>> (Wo, wo_hi, wo_lo, 128, 128);
    pack_w<<<384, 256>>>(W1, w1_hi, w1_lo, 128, 512);
    pack_w<<<384, 256>>>(W2, w2_hi, w2_lo, 512, 128);
    embed_kernel<<<ROWS, 128>>>(x, edge_attr, edge_mask, node_W, node_b, edge_W, edge_b, no_edge);

    const dim3 gN128(ROWS / 128, 1);
    const dim3 gN512(ROWS / 128, 4);

    for (int l = 0; l < LAYERS; l++) {
        // fused QKV projection: q,v1 -> big (fp32); k,v2 -> kv2h (fp16)
        gemm_tc<false,false,false,false,true><<<gN512, 256, GEMM_SMEM>>>(
            tokp, wqkv_hi + l*32768, wqkv_lo + l*32768, nullptr, nullptr,
            nullptr, nullptr, bigp, kv2hp, 128, 512);

        attn_kernel<<<BB * HH * (NN / 2), 256, 65536>>>(bigp, kv2hp, op);

        // tok = LN1(tok + o@Wo + bo)  — LN fused into epilogue, writes tok in place
        gemm_tc<true,false,true,true,false><<<gN128, 256, GEMM_SMEM>>>(
            op, wo_hi + l*8192, wo_lo + l*8192, bo + l*128, tokp,
            ln1_g + l*128, ln1_b + l*128, tokp, nullptr, 128, 128);

        // FFN up (bias+relu)
        gemm_tc<true,true,false,false,false><<<gN512, 256, GEMM_SMEM>>>(
            tokp, w1_hi + l*32768, w1_lo + l*32768, b1 + l*512, nullptr,
            nullptr, nullptr, bigp, nullptr, 128, 512);

        // tok = LN2(tok + ffn@W2 + b2) — LN fused into epilogue, writes tok in place
        gemm_tc<true,false,true,true,false><<<gN128, 256, GEMM_SMEM>>>(
            bigp, w2_hi + l*32768, w2_lo + l*32768, b2 + l*128, tokp,
            ln2_g + l*128, ln2_b + l*128, tokp, nullptr, 512, 128);
    }

    out_kernel<<<BB * NN, 128>>>(Wout, bout, (float*)d_out);
}